// round 7
// baseline (speedup 1.0000x reference)
#include <cuda_runtime.h>

#define T_SEQ   128
#define NB_     13
#define T_IN_   64
#define BQ      8
#define NBLOCKS 128
#define NTHREADS 512

// ---- shared memory layout (float indices) ----
#define SW_OFF   0        // [96 slabrows][512]: slabrow = kg*24+i  <->  W row k=kg*32+i (i<24)
#define SH_OFF   49152    // padded h: byte addr = k*32 + (k>>5)*16 + pair*8 ; 1040 floats
#define SHT_OFF  50192    // [8][132] h transposed (readout)
#define SWO_OFF  51248    // [13][132] W_out padded
#define SX_OFF   52964    // [13][12] x_t, row stride 12 floats (48B)
#define SMEM_FLOATS 53120
#define SMEM_BYTES  (SMEM_FLOATS * 4)   // 212480 <= 232448

// quad-interleaved weights: g_W4[k*512 + d*4 + g] = W_hh[(d+128g)*128 + k]
__device__ float g_W4[128 * 512];
__device__ float g_Wih4[NB_ * 512];   // g_Wih4[n*512 + d*4 + g] = W_ih[(d+128g)*13 + n]
__device__ float g_bias4[512];        // g_bias4[d*4+g] = (b_ih+b_hh)[d+128g]

typedef unsigned long long ull;

// ---------- helpers ----------
__device__ __forceinline__ unsigned sptr(const void* p) {
    return (unsigned)__cvta_generic_to_shared(p);
}
__device__ __forceinline__ ull pk2(float v) {
    ull r; unsigned u = __float_as_uint(v);
    asm("mov.b64 %0, {%1, %1};" : "=l"(r) : "r"(u));
    return r;
}
__device__ __forceinline__ ull pack2(float lo, float hi) {
    ull r;
    asm("mov.b64 %0, {%1, %2};" : "=l"(r) : "r"(__float_as_uint(lo)), "r"(__float_as_uint(hi)));
    return r;
}
__device__ __forceinline__ void fma2(ull& a, ull b, ull c) {
    asm("fma.rn.f32x2 %0, %1, %2, %0;" : "+l"(a) : "l"(b), "l"(c));
}
__device__ __forceinline__ void add2(ull& a, ull b) {
    asm("add.rn.f32x2 %0, %0, %1;" : "+l"(a) : "l"(b));
}
__device__ __forceinline__ void lds_v2u64(ull& a, ull& b, unsigned addr) {
    asm volatile("ld.shared.v2.u64 {%0, %1}, [%2];" : "=l"(a), "=l"(b) : "r"(addr));
}
__device__ __forceinline__ void sts_u64(unsigned addr, ull v) {
    asm volatile("st.shared.b64 [%0], %1;" :: "r"(addr), "l"(v) : "memory");
}
__device__ __forceinline__ float lo2(ull a) { return __uint_as_float((unsigned)(a & 0xffffffffull)); }
__device__ __forceinline__ float hi2(ull a) { return __uint_as_float((unsigned)(a >> 32)); }
__device__ __forceinline__ float sigm(float v) { return __fdividef(1.0f, 1.0f + __expf(-v)); }
__device__ __forceinline__ float tanh_(float v) { return __fdividef(2.0f, 1.0f + __expf(-2.0f * v)) - 1.0f; }

// one k, all 4 gates of dim d, 8 batch: 2 LDS.128(broadcast) + 16 fma2
__device__ __forceinline__ void do_k4(unsigned haddr, float4 wq, ull (&A)[4][4])
{
    ull h01, h23, h45, h67;
    lds_v2u64(h01, h23, haddr);
    lds_v2u64(h45, h67, haddr + 16);
    ull wi = pk2(wq.x), wf = pk2(wq.y), wg = pk2(wq.z), wo = pk2(wq.w);
    fma2(A[0][0], h01, wi); fma2(A[0][1], h23, wi); fma2(A[0][2], h45, wi); fma2(A[0][3], h67, wi);
    fma2(A[1][0], h01, wf); fma2(A[1][1], h23, wf); fma2(A[1][2], h45, wf); fma2(A[1][3], h67, wf);
    fma2(A[2][0], h01, wg); fma2(A[2][1], h23, wg); fma2(A[2][2], h45, wg); fma2(A[2][3], h67, wg);
    fma2(A[3][0], h01, wo); fma2(A[3][1], h23, wo); fma2(A[3][2], h45, wo); fma2(A[3][3], h67, wo);
}

// ---------- prep ----------
__global__ void prep_kernel(const float* __restrict__ W_hh,
                            const float* __restrict__ W_ih,
                            const float* __restrict__ b_ih,
                            const float* __restrict__ b_hh)
{
    int idx = blockIdx.x * blockDim.x + threadIdx.x;
    if (idx < 128 * 512) {
        int k = idx >> 9, r = idx & 511;
        int d = r >> 2, g = r & 3;
        g_W4[idx] = W_hh[(d + 128 * g) * 128 + k];
    }
    if (idx < NB_ * 512) {
        int n = idx >> 9, r = idx & 511;
        int d = r >> 2, g = r & 3;
        g_Wih4[idx] = W_ih[(d + 128 * g) * NB_ + n];
    }
    if (idx < 512) {
        int d = idx >> 2, g = idx & 3;
        int j = d + 128 * g;
        g_bias4[idx] = b_ih[j] + b_hh[j];
    }
}

// ---------- main persistent LSTM kernel ----------
__global__ void __launch_bounds__(NTHREADS, 1)
lstm_main(const float* __restrict__ x, const float* __restrict__ W_out,
          const float* __restrict__ b_out, float* __restrict__ out)
{
    extern __shared__ float sm[];
    float* sW  = sm + SW_OFF;
    float* sH  = sm + SH_OFF;
    float* sHT = sm + SHT_OFF;
    float* sWo = sm + SWO_OFF;
    float* sX  = sm + SX_OFF;

    const int t  = threadIdx.x;
    const int d  = t >> 2;     // 0..127
    const int kg = t & 3;      // 0..3 (within-warp: lane&3)
    const int b0 = blockIdx.x * BQ;

    // ---- cooperative smem fill ----
    {
        // weight slab: slabrow = kg*24 + i  holds W row k = kg*32 + i  (i < 24)
        const float4* src = (const float4*)g_W4;
        float4* dst = (float4*)sW;
        for (int idx = t; idx < 96 * 128; idx += NTHREADS) {
            int row = idx >> 7, col = idx & 127;
            int rkg = row / 24, ri = row - rkg * 24;
            dst[idx] = src[(rkg * 32 + ri) * 128 + col];
        }
        for (int i = t; i < NB_ * 128; i += NTHREADS) {
            int n = i >> 7, dd = i & 127;
            sWo[n * 132 + dd] = W_out[i];
        }
        for (int i = t; i < 1040; i += NTHREADS) sH[i] = 0.0f;
    }

    const unsigned hb  = sptr(sH);
    const unsigned xbb = sptr(sX);
    const unsigned myhb = hb + kg * 1040;                      // h base for k = kg*32
    const float* wsp = sW + (kg * 24) * 512 + d * 4;           // smem weights (i<24)
    const float4* gp4 = ((const float4*)g_W4) + (kg * 32 + 24) * 128 + d;  // L2 stream (i 24..31)

    // per-thread constants
    float4 bv = *(const float4*)(g_bias4 + d * 4);
    const int nbase = kg * 4;
    const int ncnt  = (kg == 3) ? 1 : 4;
    float4 wxq[4];
    #pragma unroll
    for (int m = 0; m < 4; m++) {
        if (m < ncnt) wxq[m] = __ldg(((const float4*)g_Wih4) + (nbase + m) * 128 + d);
    }

    // c-state: batches 2kg, 2kg+1 of dim d
    float cc0 = 0.0f, cc1 = 0.0f;

    // readout mapping (104 threads)
    const int yb = t / NB_;
    const int yn = t - yb * NB_;
    const bool yth = (t < BQ * NB_);
    const float bo = yth ? __ldg(b_out + yn) : 0.0f;
    const int rowx = yth ? ((b0 + yb) * (T_SEQ * NB_) + yn) : 0;

    float xreg = 0.0f;
    if (yth) {
        float x0 = x[rowx];
        sX[yn * 12 + yb] = x0;
        out[rowx] = x0;
        xreg = x[rowx + NB_];
    }
    __syncthreads();

    const unsigned hstore = hb + (unsigned)(d * 32 + (d >> 5) * 16 + kg * 8);

    for (int s = 0; s < T_SEQ - 1; s++) {
        // ---- issue L2 weight stream (rows kg*32+24 .. +31) ----
        float4 sbuf[8];
        #pragma unroll
        for (int u = 0; u < 8; u++) sbuf[u] = __ldg(gp4 + u * 128);

        // ---- accumulators ----
        ull A[4][4];
        #pragma unroll
        for (int g = 0; g < 4; g++)
            #pragma unroll
            for (int p = 0; p < 4; p++) A[g][p] = 0ull;

        // ---- k-loop: 24 smem rows ----
        #pragma unroll 1
        for (int c = 0; c < 6; c++) {
            #pragma unroll
            for (int u = 0; u < 4; u++) {
                int i = c * 4 + u;
                float4 wq = *(const float4*)(wsp + i * 512);
                do_k4(myhb + i * 32, wq, A);
            }
        }
        // ---- 8 streamed rows ----
        #pragma unroll
        for (int u = 0; u < 8; u++)
            do_k4(myhb + (24 + u) * 32, sbuf[u], A);

        // ---- x-part: this kg's n-subset, all 4 pairs ----
        #pragma unroll
        for (int m = 0; m < 4; m++) {
            if (m < ncnt) {
                int n = nbase + m;
                ull x01, x23, x45, x67;
                lds_v2u64(x01, x23, xbb + n * 48);
                lds_v2u64(x45, x67, xbb + n * 48 + 16);
                ull wi = pk2(wxq[m].x), wf = pk2(wxq[m].y), wg = pk2(wxq[m].z), wo = pk2(wxq[m].w);
                fma2(A[0][0], x01, wi); fma2(A[0][1], x23, wi); fma2(A[0][2], x45, wi); fma2(A[0][3], x67, wi);
                fma2(A[1][0], x01, wf); fma2(A[1][1], x23, wf); fma2(A[1][2], x45, wf); fma2(A[1][3], x67, wf);
                fma2(A[2][0], x01, wg); fma2(A[2][1], x23, wg); fma2(A[2][2], x45, wg); fma2(A[2][3], x67, wg);
                fma2(A[3][0], x01, wo); fma2(A[3][1], x23, wo); fma2(A[3][2], x45, wo); fma2(A[3][3], x67, wo);
            }
        }

        // ---- intra-warp reduce-scatter over the 4 kg lanes (same d) ----
        {
            const bool p2 = (kg & 2) != 0;
            const bool p1 = (kg & 1) != 0;
            // round 1: exchange with lane^2; pre-swap so slots 0,1 are "mine"
            #pragma unroll
            for (int g = 0; g < 4; g++) {
                ull a0 = A[g][0], a2 = A[g][2];
                A[g][0] = p2 ? a2 : a0;  A[g][2] = p2 ? a0 : a2;
                ull a1 = A[g][1], a3 = A[g][3];
                A[g][1] = p2 ? a3 : a1;  A[g][3] = p2 ? a1 : a3;
            }
            #pragma unroll
            for (int g = 0; g < 4; g++) {
                add2(A[g][0], __shfl_xor_sync(0xFFFFFFFFu, A[g][2], 2, 32));
                add2(A[g][1], __shfl_xor_sync(0xFFFFFFFFu, A[g][3], 2, 32));
            }
            // round 2: exchange with lane^1
            #pragma unroll
            for (int g = 0; g < 4; g++) {
                ull a0 = A[g][0], a1 = A[g][1];
                A[g][0] = p1 ? a1 : a0;  A[g][1] = p1 ? a0 : a1;
            }
            #pragma unroll
            for (int g = 0; g < 4; g++)
                add2(A[g][0], __shfl_xor_sync(0xFFFFFFFFu, A[g][1], 1, 32));
        }

        // ---- bias + activations + state update (batches 2kg, 2kg+1) ----
        {
            add2(A[0][0], pk2(bv.x));
            add2(A[1][0], pk2(bv.y));
            add2(A[2][0], pk2(bv.z));
            add2(A[3][0], pk2(bv.w));
            float i0 = sigm(lo2(A[0][0])), i1 = sigm(hi2(A[0][0]));
            float f0 = sigm(lo2(A[1][0])), f1 = sigm(hi2(A[1][0]));
            float g0 = tanh_(lo2(A[2][0])), g1 = tanh_(hi2(A[2][0]));
            float o0 = sigm(lo2(A[3][0])), o1 = sigm(hi2(A[3][0]));
            float c0 = fmaf(f0, cc0, i0 * g0);
            float c1 = fmaf(f1, cc1, i1 * g1);
            cc0 = c0; cc1 = c1;
            float h0 = o0 * tanh_(c0);
            float h1 = o1 * tanh_(c1);
            sts_u64(hstore, pack2(h0, h1));          // k-major padded layout
            sHT[(2 * kg) * 132 + d]     = h0;        // transposed for readout
            sHT[(2 * kg + 1) * 132 + d] = h1;
        }
        __syncthreads();   // barrier 1: h / hT ready

        // ---- readout: y = h @ W_out^T + b_out ----
        if (yth) {
            const float4* h4 = (const float4*)(sHT + yb * 132);
            const float4* w4 = (const float4*)(sWo + yn * 132);
            float ac0 = bo, ac1 = 0.0f, ac2 = 0.0f, ac3 = 0.0f;
            #pragma unroll 8
            for (int q = 0; q < 32; q++) {
                float4 hq = h4[q];
                float4 wq = w4[q];
                ac0 = fmaf(hq.x, wq.x, ac0);
                ac1 = fmaf(hq.y, wq.y, ac1);
                ac2 = fmaf(hq.z, wq.z, ac2);
                ac3 = fmaf(hq.w, wq.w, ac3);
            }
            float yv = (ac0 + ac1) + (ac2 + ac3);
            int sn = s + 1;
            out[rowx + sn * NB_] = yv;
            if (sn <= T_IN_) {
                sX[yn * 12 + yb] = xreg;
                if (sn + 1 <= T_IN_) xreg = x[rowx + (sn + 1) * NB_];
            } else {
                sX[yn * 12 + yb] = yv;
            }
        }
        __syncthreads();   // barrier 2: sX stable for next step
    }
}

extern "C" void kernel_launch(void* const* d_in, const int* in_sizes, int n_in,
                              void* d_out, int out_size)
{
    const float* x     = (const float*)d_in[0];
    const float* W_ih  = (const float*)d_in[1];
    const float* W_hh  = (const float*)d_in[2];
    const float* b_ih  = (const float*)d_in[3];
    const float* b_hh  = (const float*)d_in[4];
    const float* W_out = (const float*)d_in[5];
    const float* b_out = (const float*)d_in[6];
    float* out = (float*)d_out;

    cudaFuncSetAttribute(lstm_main, cudaFuncAttributeMaxDynamicSharedMemorySize, SMEM_BYTES);

    prep_kernel<<<256, 256>>>(W_hh, W_ih, b_ih, b_hh);
    lstm_main<<<NBLOCKS, NTHREADS, SMEM_BYTES>>>(x, W_out, b_out, out);
}

// round 8
// speedup vs baseline: 1.4280x; 1.4280x over previous
#include <cuda_runtime.h>

#define T_SEQ   128
#define NB_     13
#define T_IN_   64
#define BQ      8
#define NBLOCKS 128
#define NTHREADS 512

// ---- shared memory layout (float indices) ----
#define SW_OFF   0        // [80][512] pair-interleaved W_hh rows: r<40 -> k=r (kg0), r>=40 -> k=64+(r-40) (kg1)
#define SP_OFF   40960    // partials: 4096 u64 (8192 floats): idx = (slot*2+kg)*256+tt
#define SH_OFF   49152    // [128][8] h, k-major
#define SHT_OFF  50176    // [8][132] h transposed (readout)
#define SWO_OFF  51232    // [13][132] W_out padded
#define SX_OFF   52948    // [13][12] x_t (48B row stride)
#define SMEM_FLOATS 53104
#define SMEM_BYTES  (SMEM_FLOATS * 4)   // 212416 <= 232448

// pair-interleaved W_hh^T: g_WT2[k*512 + 2*tt + e] = W_hh[(tt + e*256)*128 + k]
__device__ float g_WT2[128 * 512];
__device__ float g_bias[512];

typedef unsigned long long ull;

// ---------- helpers ----------
__device__ __forceinline__ unsigned sptr(const void* p) {
    return (unsigned)__cvta_generic_to_shared(p);
}
__device__ __forceinline__ ull pk2(float v) {
    ull r; unsigned u = __float_as_uint(v);
    asm("mov.b64 %0, {%1, %1};" : "=l"(r) : "r"(u));
    return r;
}
__device__ __forceinline__ ull pack2(float lo, float hi) {
    ull r;
    asm("mov.b64 %0, {%1, %2};" : "=l"(r) : "r"(__float_as_uint(lo)), "r"(__float_as_uint(hi)));
    return r;
}
__device__ __forceinline__ void fma2(ull& a, ull b, ull c) {
    asm("fma.rn.f32x2 %0, %1, %2, %0;" : "+l"(a) : "l"(b), "l"(c));
}
__device__ __forceinline__ void add2(ull& a, ull b) {
    asm("add.rn.f32x2 %0, %0, %1;" : "+l"(a) : "l"(b));
}
__device__ __forceinline__ void lds_v2u64(ull& a, ull& b, unsigned addr) {
    asm volatile("ld.shared.v2.u64 {%0, %1}, [%2];" : "=l"(a), "=l"(b) : "r"(addr));
}
__device__ __forceinline__ ull lds_u64(unsigned addr) {
    ull v;
    asm volatile("ld.shared.b64 %0, [%1];" : "=l"(v) : "r"(addr));
    return v;
}
__device__ __forceinline__ void sts_u64(unsigned addr, ull v) {
    asm volatile("st.shared.b64 [%0], %1;" :: "r"(addr), "l"(v) : "memory");
}
__device__ __forceinline__ float lo2(ull a) { return __uint_as_float((unsigned)(a & 0xffffffffull)); }
__device__ __forceinline__ float hi2(ull a) { return __uint_as_float((unsigned)(a >> 32)); }
__device__ __forceinline__ float sigm(float v) { return __fdividef(1.0f, 1.0f + __expf(-v)); }
__device__ __forceinline__ float tanh_(float v) { return __fdividef(2.0f, 1.0f + __expf(-2.0f * v)) - 1.0f; }

// one k, 2 gate rows (tt, tt+256), 8 batch: 2 LDS.128(bcast) + 8 fma2
__device__ __forceinline__ void do_k2(unsigned haddr, float2 wp,
                                      ull (&a1)[4], ull (&a2)[4])
{
    ull h01, h23, h45, h67;
    lds_v2u64(h01, h23, haddr);
    lds_v2u64(h45, h67, haddr + 16);
    ull w1 = pk2(wp.x), w2 = pk2(wp.y);
    fma2(a1[0], h01, w1); fma2(a1[1], h23, w1); fma2(a1[2], h45, w1); fma2(a1[3], h67, w1);
    fma2(a2[0], h01, w2); fma2(a2[1], h23, w2); fma2(a2[2], h45, w2); fma2(a2[3], h67, w2);
}

// ---------- prep ----------
__global__ void prep_kernel(const float* __restrict__ W_hh,
                            const float* __restrict__ b_ih,
                            const float* __restrict__ b_hh)
{
    int idx = blockIdx.x * blockDim.x + threadIdx.x;
    if (idx < 128 * 512) {
        int k = idx >> 9, r = idx & 511;
        int tt = r >> 1, e = r & 1;
        g_WT2[idx] = W_hh[(tt + e * 256) * 128 + k];
    }
    if (idx < 512) g_bias[idx] = b_ih[idx] + b_hh[idx];
}

// ---------- main persistent LSTM kernel ----------
__global__ void __launch_bounds__(NTHREADS, 1)
lstm_main(const float* __restrict__ x, const float* __restrict__ W_ih,
          const float* __restrict__ W_out, const float* __restrict__ b_out,
          float* __restrict__ out)
{
    extern __shared__ float sm[];
    float* sW  = sm + SW_OFF;
    float* sH  = sm + SH_OFF;
    float* sHT = sm + SHT_OFF;
    float* sWo = sm + SWO_OFF;
    float* sX  = sm + SX_OFF;

    const int t  = threadIdx.x;
    const int tt = t & 255;
    const int kg = t >> 8;
    const int b0 = blockIdx.x * BQ;

    // ---- cooperative smem fill ----
    {
        const float4* src = (const float4*)g_WT2;
        float4* dst = (float4*)sW;
        for (int i = t; i < 80 * 128; i += NTHREADS) {
            int r = i >> 7, c = i & 127;
            int k = (r < 40) ? r : (64 + r - 40);
            dst[i] = src[k * 128 + c];
        }
        for (int i = t; i < NB_ * 128; i += NTHREADS) {
            int n = i >> 7, dd = i & 127;
            sWo[n * 132 + dd] = W_out[i];
        }
        for (int i = t; i < 128 * 8; i += NTHREADS) sH[i] = 0.0f;
    }

    const unsigned hb  = sptr(sH);
    const unsigned xbb = sptr(sX);
    const unsigned Pb  = sptr(sm + SP_OFF);

    // x-weights in regs: kg0 n 0..5, kg1 n 6..12
    const int nbase = (kg == 0) ? 0 : 6;
    const int ncnt  = (kg == 0) ? 6 : 7;
    float wih1[7], wih2[7];
    for (int n = 0; n < 7; n++) {
        if (n < ncnt) {
            wih1[n] = W_ih[tt * NB_ + (nbase + n)];
            wih2[n] = W_ih[(tt + 256) * NB_ + (nbase + n)];
        }
    }
    // bias folded into kg0's accumulator init
    const float bs1 = (kg == 0) ? g_bias[tt] : 0.0f;
    const float bs2 = (kg == 0) ? g_bias[tt + 256] : 0.0f;

    // update identity: dim d, batch-pair q
    const int d = t & 127;
    const int q = t >> 7;           // 0..3 ; kg = q>>1
    float cc0 = 0.0f, cc1 = 0.0f;   // c-state for batches 2q, 2q+1

    // readout mapping (104 threads, all in kg0)
    const int yb = t / NB_;
    const int yn = t - yb * NB_;
    const bool yth = (t < BQ * NB_);
    const float bo = yth ? __ldg(b_out + yn) : 0.0f;
    const int rowx = yth ? ((b0 + yb) * (T_SEQ * NB_) + yn) : 0;

    float xreg = 0.0f;
    if (yth) {
        float x0 = x[rowx];
        sX[yn * 12 + yb] = x0;
        out[rowx] = x0;                  // out[:,0] = x[:,0]
        xreg = x[rowx + NB_];            // prefetch x[:,1]
    }
    __syncthreads();

    // per-kg pointers
    const float* swb = sW + (kg * 40) * 512;            // 40 resident rows
    const unsigned myH = hb + (unsigned)(kg * 2048);    // h base (k = 64*kg)
    const float2* gs = ((const float2*)g_WT2) + (64 * kg + 40) * 256 + tt;  // streamed k rows

    for (int s = 0; s < T_SEQ - 1; s++) {
        // ---- hidden readout of y_s (concurrent with h-GEMM below) ----
        if (s > 0 && yth) {
            const float4* h4 = (const float4*)(sHT + yb * 132);
            const float4* w4 = (const float4*)(sWo + yn * 132);
            float ac0 = bo, ac1 = 0.0f, ac2 = 0.0f, ac3 = 0.0f;
            #pragma unroll 8
            for (int qq = 0; qq < 32; qq++) {
                float4 hq = h4[qq];
                float4 wq = w4[qq];
                ac0 = fmaf(hq.x, wq.x, ac0);
                ac1 = fmaf(hq.y, wq.y, ac1);
                ac2 = fmaf(hq.z, wq.z, ac2);
                ac3 = fmaf(hq.w, wq.w, ac3);
            }
            float yv = (ac0 + ac1) + (ac2 + ac3);
            out[rowx + s * NB_] = yv;
            if (s <= T_IN_) {
                sX[yn * 12 + yb] = xreg;                       // teacher input x[:,s]
                if (s + 1 <= T_IN_) xreg = x[rowx + (s + 1) * NB_];
            } else {
                sX[yn * 12 + yb] = yv;                         // autoregressive feedback
            }
        }

        // ---- h-GEMM: this kg's 64 k-rows ----
        ull a1[4], a2[4];
        {
            ull bp1 = pk2(bs1), bp2 = pk2(bs2);
            a1[0] = bp1; a1[1] = bp1; a1[2] = bp1; a1[3] = bp1;
            a2[0] = bp2; a2[1] = bp2; a2[2] = bp2; a2[3] = bp2;
        }
        // issue L2 stream chunks 0,1 (rows 40..55 local)
        float2 sb0[8], sb1[8];
        #pragma unroll
        for (int u = 0; u < 8; u++) sb0[u] = __ldg(gs + u * 256);
        #pragma unroll
        for (int u = 0; u < 8; u++) sb1[u] = __ldg(gs + (8 + u) * 256);

        // resident rows 0..39
        #pragma unroll 1
        for (int r = 0; r < 40; r += 4) {
            #pragma unroll
            for (int u = 0; u < 4; u++) {
                float2 wp = *(const float2*)(swb + (r + u) * 512 + 2 * tt);
                do_k2(myH + (r + u) * 32, wp, a1, a2);
            }
        }
        // consume chunk0 (rows 40..47), refill into sb0 (rows 56..63)
        #pragma unroll
        for (int u = 0; u < 8; u++) {
            float2 wp = sb0[u];
            sb0[u] = __ldg(gs + (16 + u) * 256);
            do_k2(myH + (40 + u) * 32, wp, a1, a2);
        }
        // consume chunk1 (rows 48..55)
        #pragma unroll
        for (int u = 0; u < 8; u++) do_k2(myH + (48 + u) * 32, sb1[u], a1, a2);
        // consume chunk2 (rows 56..63)
        #pragma unroll
        for (int u = 0; u < 8; u++) do_k2(myH + (56 + u) * 32, sb0[u], a1, a2);

        __syncthreads();   // B1: sX written by readout; everyone done with prior sX reads

        // ---- x-part: this kg's n-subset ----
        #pragma unroll
        for (int n = 0; n < 7; n++) {
            if (n < ncnt) {
                ull x01, x23, x45, x67;
                lds_v2u64(x01, x23, xbb + (nbase + n) * 48);
                lds_v2u64(x45, x67, xbb + (nbase + n) * 48 + 16);
                ull w1 = pk2(wih1[n]), w2 = pk2(wih2[n]);
                fma2(a1[0], x01, w1); fma2(a1[1], x23, w1); fma2(a1[2], x45, w1); fma2(a1[3], x67, w1);
                fma2(a2[0], x01, w2); fma2(a2[1], x23, w2); fma2(a2[2], x45, w2); fma2(a2[3], x67, w2);
            }
        }

        // ---- publish all 8 partials: slot p -> a1[p], slot 4+p -> a2[p] ----
        #pragma unroll
        for (int p = 0; p < 4; p++) {
            sts_u64(Pb + (unsigned)(((p * 2 + kg) * 256 + tt) * 8), a1[p]);
            sts_u64(Pb + (unsigned)((((4 + p) * 2 + kg) * 256 + tt) * 8), a2[p]);
        }
        __syncthreads();   // B2: partials ready

        // ---- update (all 512 threads): dim d, batch pair q ----
        {
            // gate rows: i=d (a1 of tt=d), f=d+128 (a1 of tt=d+128), g=d (a2), o=d+128 (a2)
            ull Ai = lds_u64(Pb + (unsigned)(((q * 2 + 0) * 256 + d) * 8));
            add2(Ai,  lds_u64(Pb + (unsigned)(((q * 2 + 1) * 256 + d) * 8)));
            ull Af = lds_u64(Pb + (unsigned)(((q * 2 + 0) * 256 + d + 128) * 8));
            add2(Af,  lds_u64(Pb + (unsigned)(((q * 2 + 1) * 256 + d + 128) * 8)));
            ull Ag = lds_u64(Pb + (unsigned)((((4 + q) * 2 + 0) * 256 + d) * 8));
            add2(Ag,  lds_u64(Pb + (unsigned)((((4 + q) * 2 + 1) * 256 + d) * 8)));
            ull Ao = lds_u64(Pb + (unsigned)((((4 + q) * 2 + 0) * 256 + d + 128) * 8));
            add2(Ao,  lds_u64(Pb + (unsigned)((((4 + q) * 2 + 1) * 256 + d + 128) * 8)));

            float i0 = sigm(lo2(Ai)), i1 = sigm(hi2(Ai));
            float f0 = sigm(lo2(Af)), f1 = sigm(hi2(Af));
            float g0 = tanh_(lo2(Ag)), g1 = tanh_(hi2(Ag));
            float o0 = sigm(lo2(Ao)), o1 = sigm(hi2(Ao));
            float c0 = fmaf(f0, cc0, i0 * g0);
            float c1 = fmaf(f1, cc1, i1 * g1);
            cc0 = c0; cc1 = c1;
            float h0 = o0 * tanh_(c0);
            float h1 = o1 * tanh_(c1);

            sts_u64(hb + (unsigned)(d * 32 + q * 8), pack2(h0, h1));  // k-major for GEMM
            sHT[(2 * q) * 132 + d]     = h0;                          // transposed for readout
            sHT[(2 * q + 1) * 132 + d] = h1;
        }
        __syncthreads();   // B3: h ready for next step's GEMM + readout
    }

    // ---- final readout: y_127 ----
    if (yth) {
        const float4* h4 = (const float4*)(sHT + yb * 132);
        const float4* w4 = (const float4*)(sWo + yn * 132);
        float ac0 = bo, ac1 = 0.0f, ac2 = 0.0f, ac3 = 0.0f;
        #pragma unroll 8
        for (int qq = 0; qq < 32; qq++) {
            float4 hq = h4[qq];
            float4 wq = w4[qq];
            ac0 = fmaf(hq.x, wq.x, ac0);
            ac1 = fmaf(hq.y, wq.y, ac1);
            ac2 = fmaf(hq.z, wq.z, ac2);
            ac3 = fmaf(hq.w, wq.w, ac3);
        }
        out[rowx + (T_SEQ - 1) * NB_] = (ac0 + ac1) + (ac2 + ac3);
    }
}

extern "C" void kernel_launch(void* const* d_in, const int* in_sizes, int n_in,
                              void* d_out, int out_size)
{
    const float* x     = (const float*)d_in[0];
    const float* W_ih  = (const float*)d_in[1];
    const float* W_hh  = (const float*)d_in[2];
    const float* b_ih  = (const float*)d_in[3];
    const float* b_hh  = (const float*)d_in[4];
    const float* W_out = (const float*)d_in[5];
    const float* b_out = (const float*)d_in[6];
    float* out = (float*)d_out;

    cudaFuncSetAttribute(lstm_main, cudaFuncAttributeMaxDynamicSharedMemorySize, SMEM_BYTES);

    prep_kernel<<<256, 256>>>(W_hh, b_ih, b_hh);
    lstm_main<<<NBLOCKS, NTHREADS, SMEM_BYTES>>>(x, W_ih, W_out, b_out, out);
}